// round 2
// baseline (speedup 1.0000x reference)
#include <cuda_runtime.h>
#include <math.h>

#define D        64
#define NC       16
#define NS       136
#define NITEMS   5120        // 512 * 10
#define TPB      256
#define WPB      8           // warps per block, 1 item per warp
#define NB       (NITEMS / WPB)  // 640 blocks

__device__ double       g_partial[NB];
__device__ unsigned int g_count;   // zero-initialized; reset by last block each launch

__global__ __launch_bounds__(TPB)
void latent_fused(const float* __restrict__ z, const float* __restrict__ mu,
                  const float* __restrict__ pi, const int* __restrict__ A,
                  const int* __restrict__ B, float* __restrict__ out) {
    __shared__ float  s_mu[D * NC];        // [d][c]
    __shared__ float  s_invsig[NS], s_cab[NS], s_gbb[NS], s_lpi[NS];
    __shared__ int    s_A[NS], s_B[NS];
    __shared__ float  s_dz[WPB][NC];
    __shared__ float  s_z[WPB][D];
    __shared__ float  s_red[TPB];
    __shared__ double s_wsum[WPB];
    __shared__ double s_fin[TPB];
    __shared__ int    s_islast;

    const float LOG2PI = 1.8378770664093453f;
    const float BASE   = -32.0f * LOG2PI;   // -0.5 * d * log(2pi), d=64

    int t    = threadIdx.x;
    int w    = t >> 5, lane = t & 31;
    int item = blockIdx.x * WPB + w;

    // issue z load ASAP (independent of shared staging)
    const float2* zp = (const float2*)(z + item * D);
    float2 zv = zp[lane];

    // ---- stage mu, A, B, exp(pi) ----
    #pragma unroll
    for (int i = t; i < D * NC; i += TPB) s_mu[i] = mu[i];
    float piv = 0.f;
    if (t < NS) { s_A[t] = A[t]; s_B[t] = B[t]; piv = pi[t]; }
    s_red[t] = (t < NS) ? expf(piv) : 0.f;
    s_z[w][2 * lane]     = zv.x;
    s_z[w][2 * lane + 1] = zv.y;
    __syncthreads();

    // ---- per-state constants (diff-form => diagonal gives EXACT 0) ----
    if (t < NS) {
        int a = s_A[t], b = s_B[t];
        float is0 = 0.f, is1 = 0.f, cb0 = 0.f, cb1 = 0.f, gb0 = 0.f, gb1 = 0.f;
        #pragma unroll
        for (int d = 0; d < D; d += 2) {
            float ma0 = s_mu[d * NC + a],       mb0 = s_mu[d * NC + b];
            float ma1 = s_mu[(d + 1) * NC + a], mb1 = s_mu[(d + 1) * NC + b];
            float df0 = mb0 - ma0, df1 = mb1 - ma1;
            is0 = fmaf(df0, df0, is0);  is1 = fmaf(df1, df1, is1);
            cb0 = fmaf(df0, mb0, cb0);  cb1 = fmaf(df1, mb1, cb1);
            gb0 = fmaf(mb0, mb0, gb0);  gb1 = fmaf(mb1, mb1, gb1);
        }
        s_invsig[t] = is0 + is1; s_cab[t] = cb0 + cb1; s_gbb[t] = gb0 + gb1;
    }

    // ---- softmax(pi) denominator: per-warp redundant (no extra sync) ----
    if (w < (NS + 31) / 32) {
        float ps = 0.f;
        #pragma unroll
        for (int i = 0; i < TPB / 32; i++) ps += s_red[lane + 32 * i];
        #pragma unroll
        for (int off = 16; off; off >>= 1)
            ps += __shfl_xor_sync(0xffffffffu, ps, off);
        if (t < NS) s_lpi[t] = logf(expf(piv) / ps + 1e-12f);
    }

    // ---- per-item: |z|^2 and 16 cluster dots ----
    float zn = fmaf(zv.x, zv.x, zv.y * zv.y);
    #pragma unroll
    for (int off = 16; off; off >>= 1)
        zn += __shfl_xor_sync(0xffffffffu, zn, off);

    if (lane < NC) {
        float a0 = 0.f, a1 = 0.f, a2 = 0.f, a3 = 0.f;
        const float* zr = s_z[w];
        #pragma unroll
        for (int d = 0; d < D; d += 4) {
            a0 = fmaf(zr[d],     s_mu[d * NC + lane],       a0);
            a1 = fmaf(zr[d + 1], s_mu[(d + 1) * NC + lane], a1);
            a2 = fmaf(zr[d + 2], s_mu[(d + 2) * NC + lane], a2);
            a3 = fmaf(zr[d + 3], s_mu[(d + 3) * NC + lane], a3);
        }
        s_dz[w][lane] = (a0 + a1) + (a2 + a3);
    }
    __syncthreads();

    // ---- 136 states striped over 32 lanes, online logsumexp ----
    float m = -1e30f, acc = 0.f;
    #pragma unroll
    for (int k = 0; k < 5; k++) {
        int s = lane + 32 * k;
        if (s < NS) {
            int a = s_A[s], b = s_B[s];
            float dzB    = s_dz[w][b];
            float invsig = s_invsig[s];
            float sq_a2  = zn - 2.f * dzB + s_gbb[s];
            float val;
            if (invsig == 0.f) {
                val = BASE + s_lpi[s] - 0.5f * sq_a2;
            } else {
                float dzA   = s_dz[w][a];
                float dot12 = (dzB - dzA) - s_cab[s];
                float mu_   = -dot12 / invsig;
                float tt    = fmaf(mu_ * mu_, invsig, -sq_a2);
                float sd    = sqrtf(invsig + 1e-12f);
                float cdfd  = normcdff((1.f - mu_) * sd) - normcdff(-mu_ * sd);
                val = BASE + s_lpi[s]
                    + 0.5f * (LOG2PI - logf(invsig + 1e-12f) + tt)
                    + logf(cdfd + 1e-12f);
            }
            if (val > m) { acc = acc * expf(m - val) + 1.f; m = val; }
            else         { acc += expf(val - m); }
        }
    }

    #pragma unroll
    for (int off = 16; off; off >>= 1) {
        float m2 = __shfl_xor_sync(0xffffffffu, m,   off);
        float a2 = __shfl_xor_sync(0xffffffffu, acc, off);
        float M  = fmaxf(m, m2);
        acc = acc * expf(m - M) + a2 * expf(m2 - M);
        m = M;
    }
    float lse = m + logf(acc);

    if (lane == 0) s_wsum[w] = (double)lse;
    __syncthreads();

    // ---- block partial + last-block finalize (deterministic) ----
    if (t == 0) {
        double ssum = 0.0;
        #pragma unroll
        for (int i = 0; i < WPB; i++) ssum += s_wsum[i];
        g_partial[blockIdx.x] = ssum;
        __threadfence();
        unsigned int tick = atomicAdd(&g_count, 1u);
        s_islast = (tick == NB - 1u);
    }
    __syncthreads();

    if (s_islast) {
        double v = 0.0;
        for (int i = t; i < NB; i += TPB) v += g_partial[i];
        s_fin[t] = v;
        __syncthreads();
        #pragma unroll
        for (int off = TPB / 2; off > 0; off >>= 1) {
            if (t < off) s_fin[t] += s_fin[t + off];
            __syncthreads();
        }
        if (t == 0) {
            out[0] = (float)(s_fin[0] / (double)NITEMS);
            g_count = 0;   // reset for next graph replay
        }
    }
}

extern "C" void kernel_launch(void* const* d_in, const int* in_sizes, int n_in,
                              void* d_out, int out_size) {
    const float* z  = (const float*)d_in[0];
    const float* mu = (const float*)d_in[1];
    const float* pi = (const float*)d_in[2];
    const int*   A  = (const int*)d_in[3];
    const int*   B  = (const int*)d_in[4];
    float* out = (float*)d_out;
    (void)in_sizes; (void)n_in; (void)out_size;

    latent_fused<<<NB, TPB>>>(z, mu, pi, A, B, out);
}